// round 14
// baseline (speedup 1.0000x reference)
#include <cuda_runtime.h>
#include <math.h>

#define TT   512
#define BBT  256
#define OUTD 500

typedef unsigned long long ull;

// static device scratch (no allocation)
__device__ float g_h1buf[BBT * TT * 10];   // h1 AFTER step t
__device__ float g_h2buf[BBT * TT * 10];   // h2_shift at t

// ---------------- packed f32x2 helpers ----------------
__device__ __forceinline__ ull pack2(float lo, float hi) {
    ull u; asm("mov.b64 %0,{%1,%2};" : "=l"(u) : "f"(lo), "f"(hi)); return u;
}
__device__ __forceinline__ ull ffma2(ull a, ull b, ull c) {
    ull d; asm("fma.rn.f32x2 %0,%1,%2,%3;" : "=l"(d) : "l"(a), "l"(b), "l"(c)); return d;
}
__device__ __forceinline__ float red2(ull u) {
    float lo, hi; asm("mov.b64 {%0,%1},%2;" : "=f"(lo), "=f"(hi) : "l"(u)); return lo + hi;
}
template <int NP>
__device__ __forceinline__ float dot_rw(const ull* __restrict__ w,
                                        const ull* __restrict__ v) {
    ull a0 = 0ull, a1 = 0ull;
#pragma unroll
    for (int p = 0; p < NP; p += 2) {
        a0 = ffma2(w[p], v[p], a0);
        if (p + 1 < NP) a1 = ffma2(w[p + 1], v[p + 1], a1);
    }
    return red2(a0) + red2(a1);
}
template <int NP>
__device__ __forceinline__ float dot4(const ull* __restrict__ w,
                                      const ull* __restrict__ v) {
    ull a0 = 0ull, a1 = 0ull, a2 = 0ull, a3 = 0ull;
#pragma unroll
    for (int p = 0; p < NP; p += 4) {
        a0 = ffma2(w[p], v[p], a0);
        if (p + 1 < NP) a1 = ffma2(w[p + 1], v[p + 1], a1);
        if (p + 2 < NP) a2 = ffma2(w[p + 2], v[p + 2], a2);
        if (p + 3 < NP) a3 = ffma2(w[p + 3], v[p + 3], a3);
    }
    return (red2(a0) + red2(a1)) + (red2(a2) + red2(a3));
}

// ---------------- fast activations ----------------
__device__ __forceinline__ float sigm(float x) {
    return __fdividef(1.0f, 1.0f + __expf(-x));
}
__device__ __forceinline__ float tanh_f(float x) {
    x = fminf(fmaxf(x, -15.0f), 15.0f);
    float e = __expf(2.0f * x);
    return __fdividef(e - 1.0f, e + 1.0f);
}
__device__ __forceinline__ float softplus_f(float x) {
    return fmaxf(x, 0.0f) + __logf(1.0f + __expf(-fabsf(x)));
}

// =====================================================================
// Kernel 1: scans. 128 blocks x 64 threads.
//   warp 0: h1 scans for BOTH batches (interleaved chains)
//   warp 1: h2 scans for BOTH batches
// =====================================================================
__global__ void __launch_bounds__(64, 1)
scan_kernel(const float* __restrict__ x, const float* __restrict__ eps,
            const float* __restrict__ W_ih1, const float* __restrict__ W_hh1,
            const float* __restrict__ b_ih1, const float* __restrict__ b_hh1,
            const float* __restrict__ W_ih2, const float* __restrict__ W_hh2,
            const float* __restrict__ b_ih2, const float* __restrict__ b_hh2,
            const float* __restrict__ dzW1, const float* __restrict__ dzb1,
            const float* __restrict__ dzWloc, const float* __restrict__ dzbloc,
            const float* __restrict__ dzWsc, const float* __restrict__ dzbsc,
            const float* __restrict__ h1_0, const float* __restrict__ h2_0,
            float* __restrict__ out) {
    __shared__ ull s_wa[30 * 51];                     // W_ih1 packed pairs, pitch 51
    __shared__ __align__(16) float s_z[2][104];       // z_t per batch
    __shared__ __align__(16) float s_x[3][2][104];    // x triple buffer (RNN2)
    __shared__ __align__(16) float s_h1[2][12];       // h1 state per batch
    __shared__ __align__(16) float s_hdz[2][20];
    __shared__ __align__(16) float s_h2s[2][12];      // h2 state per batch

    const int tid  = threadIdx.x;
    const int lane = tid & 31;
    const int wid  = tid >> 5;
    const int b0   = blockIdx.x * 2;

    // cooperative: W_ih1 -> shared (packed pairs)
    for (int i = tid; i < 1500; i += 64) {
        int j = i / 50, p = i % 50;
        s_wa[j * 51 + p] = pack2(W_ih1[j * 100 + 2 * p], W_ih1[j * 100 + 2 * p + 1]);
    }
    // x slots 0,1
    for (int i = tid; i < 100; i += 64) {
        int s = i / 50, r = i % 50, bb = r / 25, f = r % 25;
        ((float4*)&s_x[s][bb][0])[f] =
            ((const float4*)(x + ((size_t)(b0 + bb) * TT + s) * 100))[f];
    }
    if (tid < 10) { s_h1[0][tid] = h1_0[tid]; s_h1[1][tid] = h1_0[tid]; }
    if (tid < 10) { s_h2s[0][tid] = h2_0[tid]; s_h2s[1][tid] = h2_0[tid]; }

    if (wid == 0) {
        // ================= h1 scan warp (2 batches) =================
        const int nr = (lane < 4) ? 4 : 3;
        ull wzl[4][10], wzs[4][10];
        float bzl4[4], bzs4[4], er4[2][4];
        float dzr[10], whh1r[10];
        float bdz = 0.f, bhh1 = 0.f, bih1 = 0.f;
        float h1p0 = 0.f, h1p1 = 0.f;
#pragma unroll
        for (int m = 0; m < 4; m++) {
            int row = lane + 32 * m;
            bzl4[m] = bzs4[m] = er4[0][m] = er4[1][m] = 0.f;
#pragma unroll
            for (int q = 0; q < 10; q++) { wzl[m][q] = 0ull; wzs[m][q] = 0ull; }
            if (row < 100) {
                const float2* pl = (const float2*)(dzWloc + row * 20);
                const float2* ps = (const float2*)(dzWsc + row * 20);
#pragma unroll
                for (int q = 0; q < 10; q++) {
                    float2 a = pl[q]; wzl[m][q] = pack2(a.x, a.y);
                    float2 b = ps[q]; wzs[m][q] = pack2(b.x, b.y);
                }
                bzl4[m] = dzbloc[row]; bzs4[m] = dzbsc[row];
                er4[0][m] = eps[((size_t)(b0 + 0) * TT) * 100 + row];
                er4[1][m] = eps[((size_t)(b0 + 1) * TT) * 100 + row];
            }
        }
#pragma unroll
        for (int k = 0; k < 10; k++) { dzr[k] = 0.f; whh1r[k] = 0.f; }
        if (lane < 20) {
#pragma unroll
            for (int k = 0; k < 10; k++) dzr[k] = dzW1[lane * 10 + k];
            bdz = dzb1[lane];
        }
        if (lane < 30) {
#pragma unroll
            for (int k = 0; k < 10; k++) whh1r[k] = W_hh1[lane * 10 + k];
            bhh1 = b_hh1[lane]; bih1 = b_ih1[lane];
        }
        if (lane < 10) { h1p0 = h1_0[lane]; h1p1 = h1_0[lane]; }
        __syncthreads();

        for (int t = 0; t < TT; t++) {
            // --- hdz + gh1 for both batches from s_h1 (LDS broadcast) ---
            float adz0 = bdz, adz1 = bdz, agh0 = bhh1, agh1 = bhh1;
#pragma unroll
            for (int k = 0; k < 10; k++) {
                float h0 = s_h1[0][k], h1v = s_h1[1][k];
                adz0 = fmaf(dzr[k], h0, adz0);
                adz1 = fmaf(dzr[k], h1v, adz1);
                agh0 = fmaf(whh1r[k], h0, agh0);
                agh1 = fmaf(whh1r[k], h1v, agh1);
            }
            if (lane < 20) {
                s_hdz[0][lane] = fmaxf(adz0, 0.0f);
                s_hdz[1][lane] = fmaxf(adz1, 0.0f);
            }
            __syncwarp();
            // --- z head: 3-4 rows per lane x 2 batches ---
            const ull* hz0 = (const ull*)&s_hdz[0][0];
            const ull* hz1 = (const ull*)&s_hdz[1][0];
            float* o0 = out + ((size_t)(b0 + 0) * TT + t) * OUTD;
            float* o1 = out + ((size_t)(b0 + 1) * TT + t) * OUTD;
#pragma unroll
            for (int m = 0; m < 4; m++) {
                int row = lane + 32 * m;
                if (m < nr) {
                    float zl0 = dot_rw<10>(wzl[m], hz0) + bzl4[m];
                    float zl1 = dot_rw<10>(wzl[m], hz1) + bzl4[m];
                    float zs0 = softplus_f(dot_rw<10>(wzs[m], hz0) + bzs4[m]);
                    float zs1 = softplus_f(dot_rw<10>(wzs[m], hz1) + bzs4[m]);
                    float zt0 = fmaf(zs0, er4[0][m], zl0);
                    float zt1 = fmaf(zs1, er4[1][m], zl1);
                    o0[200 + row] = zl0; o0[300 + row] = zs0; o0[400 + row] = zt0;
                    o1[200 + row] = zl1; o1[300 + row] = zs1; o1[400 + row] = zt1;
                    s_z[0][row] = zt0; s_z[1][row] = zt1;
                }
            }
            if (t + 1 < TT) {                          // eps prefetch (t+1)
#pragma unroll
                for (int m = 0; m < 4; m++) {
                    int row = lane + 32 * m;
                    if (m < nr && row < 100) {
                        er4[0][m] = eps[((size_t)(b0 + 0) * TT + t + 1) * 100 + row];
                        er4[1][m] = eps[((size_t)(b0 + 1) * TT + t + 1) * 100 + row];
                    }
                }
            }
            __syncwarp();
            // --- gi1 both batches (shared weights) ---
            float g0 = 0.f, g1 = 0.f;
            if (lane < 30) {
                const ull* wr = s_wa + lane * 51;
                g0 = dot4<50>(wr, (const ull*)&s_z[0][0]) + bih1;
                g1 = dot4<50>(wr, (const ull*)&s_z[1][0]) + bih1;
            }
            float gA0  = __shfl_sync(0xFFFFFFFFu, g0,   (lane + 10) & 31);
            float gB0  = __shfl_sync(0xFFFFFFFFu, g0,   (lane + 20) & 31);
            float gA1  = __shfl_sync(0xFFFFFFFFu, g1,   (lane + 10) & 31);
            float gB1  = __shfl_sync(0xFFFFFFFFu, g1,   (lane + 20) & 31);
            float ghA0 = __shfl_sync(0xFFFFFFFFu, agh0, (lane + 10) & 31);
            float ghB0 = __shfl_sync(0xFFFFFFFFu, agh0, (lane + 20) & 31);
            float ghA1 = __shfl_sync(0xFFFFFFFFu, agh1, (lane + 10) & 31);
            float ghB1 = __shfl_sync(0xFFFFFFFFu, agh1, (lane + 20) & 31);
            if (lane < 10) {
                float r0  = sigm(g0 + agh0);
                float r1  = sigm(g1 + agh1);
                float u0  = sigm(gA0 + ghA0);
                float u1  = sigm(gA1 + ghA1);
                float n0  = tanh_f(fmaf(r0, ghB0, gB0));
                float n1  = tanh_f(fmaf(r1, ghB1, gB1));
                float h1n0 = fmaf(u0, h1p0 - n0, n0);
                float h1n1 = fmaf(u1, h1p1 - n1, n1);
                h1p0 = h1n0; h1p1 = h1n1;
                s_h1[0][lane] = h1n0;
                s_h1[1][lane] = h1n1;
                g_h1buf[((size_t)(b0 + 0) * TT + t) * 10 + lane] = h1n0;
                g_h1buf[((size_t)(b0 + 1) * TT + t) * 10 + lane] = h1n1;
            }
            __syncwarp();
        }
    } else {
        // ================= h2 (RNN2) scan warp (2 batches) =================
        ull wih2r[50];
        float whh2r[10];
        float bih2r = 0.f, bhh2r = 0.f, h2o0 = 0.f, h2o1 = 0.f;
#pragma unroll
        for (int q = 0; q < 50; q++) wih2r[q] = 0ull;
#pragma unroll
        for (int k = 0; k < 10; k++) whh2r[k] = 0.f;
        if (lane < 30) {
            const float2* p = (const float2*)(W_ih2 + lane * 100);
#pragma unroll
            for (int q = 0; q < 50; q++) { float2 v = p[q]; wih2r[q] = pack2(v.x, v.y); }
#pragma unroll
            for (int k = 0; k < 10; k++) whh2r[k] = W_hh2[lane * 10 + k];
            bih2r = b_ih2[lane]; bhh2r = b_hh2[lane];
        }
        if (lane < 10) { h2o0 = h2_0[lane]; h2o1 = h2_0[lane]; }
        __syncthreads();

        float4 pre0 = make_float4(0.f, 0.f, 0.f, 0.f);
        float4 pre1 = make_float4(0.f, 0.f, 0.f, 0.f);
        for (int t = 0; t < TT; t++) {
            // publish h2_shift[t] (state BEFORE consuming x_t)
            if (lane < 10) {
                g_h2buf[((size_t)(b0 + 0) * TT + t) * 10 + lane] = h2o0;
                g_h2buf[((size_t)(b0 + 1) * TT + t) * 10 + lane] = h2o1;
            }
            if (lane < 25 && t + 2 < TT) {             // x(t+2) prefetch
                pre0 = ((const float4*)(x + ((size_t)(b0 + 0) * TT + t + 2) * 100))[lane];
                pre1 = ((const float4*)(x + ((size_t)(b0 + 1) * TT + t + 2) * 100))[lane];
            }
            // gi2 + gh2 both batches
            float g0 = 0.f, g1 = 0.f, gh0 = bhh2r, gh1v = bhh2r;
            if (lane < 30) {
                g0 = dot4<50>(wih2r, (const ull*)&s_x[t % 3][0][0]) + bih2r;
                g1 = dot4<50>(wih2r, (const ull*)&s_x[t % 3][1][0]) + bih2r;
#pragma unroll
                for (int k = 0; k < 10; k++) {
                    gh0  = fmaf(whh2r[k], s_h2s[0][k], gh0);
                    gh1v = fmaf(whh2r[k], s_h2s[1][k], gh1v);
                }
            }
            float gA0  = __shfl_sync(0xFFFFFFFFu, g0,   (lane + 10) & 31);
            float gB0  = __shfl_sync(0xFFFFFFFFu, g0,   (lane + 20) & 31);
            float gA1  = __shfl_sync(0xFFFFFFFFu, g1,   (lane + 10) & 31);
            float gB1  = __shfl_sync(0xFFFFFFFFu, g1,   (lane + 20) & 31);
            float ghA0 = __shfl_sync(0xFFFFFFFFu, gh0,  (lane + 10) & 31);
            float ghB0 = __shfl_sync(0xFFFFFFFFu, gh0,  (lane + 20) & 31);
            float ghA1 = __shfl_sync(0xFFFFFFFFu, gh1v, (lane + 10) & 31);
            float ghB1 = __shfl_sync(0xFFFFFFFFu, gh1v, (lane + 20) & 31);
            if (lane < 10) {
                float r0 = sigm(g0 + gh0);
                float r1 = sigm(g1 + gh1v);
                float u0 = sigm(gA0 + ghA0);
                float u1 = sigm(gA1 + ghA1);
                float n0 = tanh_f(fmaf(r0, ghB0, gB0));
                float n1 = tanh_f(fmaf(r1, ghB1, gB1));
                float h2n0 = fmaf(u0, h2o0 - n0, n0);
                float h2n1 = fmaf(u1, h2o1 - n1, n1);
                h2o0 = h2n0; h2o1 = h2n1;
                s_h2s[0][lane] = h2n0;
                s_h2s[1][lane] = h2n1;
            }
            if (lane < 25 && t + 2 < TT) {
                ((float4*)&s_x[(t + 2) % 3][0][0])[lane] = pre0;
                ((float4*)&s_x[(t + 2) % 3][1][0])[lane] = pre1;
            }
            __syncwarp();
        }
    }
}

// =====================================================================
// Kernel 2: x-head. 512 blocks (batch, half) x 256 threads.
// =====================================================================
__global__ void __launch_bounds__(256, 2)
xhead_kernel(const float* __restrict__ dxW1, const float* __restrict__ dxb1,
             const float* __restrict__ dxWloc, const float* __restrict__ dxbloc,
             const float* __restrict__ dxWsc, const float* __restrict__ dxbsc,
             float* __restrict__ out) {
    __shared__ __align__(16) float s_cat[16][20];
    __shared__ __align__(16) float s_hdx[16][20];
    __shared__ float s_W1[400], s_b1[20];

    const int tid  = threadIdx.x;
    const int b    = blockIdx.x >> 1;
    const int half = blockIdx.x & 1;

    for (int i = tid; i < 400; i += 256) s_W1[i] = dxW1[i];
    if (tid < 20) s_b1[tid] = dxb1[tid];

    ull wx[10];
    float bx = 0.f;
    int j = 0, head = 0;
    if (tid < 200) {
        head = tid / 100; j = tid % 100;
        const float2* p = (const float2*)((head ? dxWsc : dxWloc) + j * 20);
#pragma unroll
        for (int q = 0; q < 10; q++) { float2 v = p[q]; wx[q] = pack2(v.x, v.y); }
        bx = head ? dxbsc[j] : dxbloc[j];
    }
    __syncthreads();

    for (int c = half * 16; c < half * 16 + 16; c++) {
        const int t0 = c * 16;
        for (int i = tid; i < 320; i += 256) {
            int tt = i / 20, k = i % 20;
            s_cat[tt][k] = (k < 10)
                ? g_h1buf[((size_t)b * TT + t0 + tt) * 10 + k]
                : g_h2buf[((size_t)b * TT + t0 + tt) * 10 + (k - 10)];
        }
        __syncthreads();
        for (int i = tid; i < 320; i += 256) {
            int tt = i / 20, jj = i % 20;
            float a = s_b1[jj];
#pragma unroll
            for (int k = 0; k < 20; k++) a = fmaf(s_W1[jj * 20 + k], s_cat[tt][k], a);
            s_hdx[tt][jj] = fmaxf(a, 0.0f);
        }
        __syncthreads();
        if (tid < 200) {
#pragma unroll 4
            for (int tt = 0; tt < 16; tt++) {
                float v = dot_rw<10>(wx, (const ull*)&s_hdx[tt][0]) + bx;
                if (head) v = softplus_f(v);
                out[((size_t)b * TT + t0 + tt) * OUTD + head * 100 + j] = v;
            }
        }
        __syncthreads();
    }
}

extern "C" void kernel_launch(void* const* d_in, const int* in_sizes, int n_in,
                              void* d_out, int out_size) {
    const float* x      = (const float*)d_in[0];
    const float* eps    = (const float*)d_in[1];
    const float* W_ih1  = (const float*)d_in[2];
    const float* W_hh1  = (const float*)d_in[3];
    const float* b_ih1  = (const float*)d_in[4];
    const float* b_hh1  = (const float*)d_in[5];
    const float* W_ih2  = (const float*)d_in[6];
    const float* W_hh2  = (const float*)d_in[7];
    const float* b_ih2  = (const float*)d_in[8];
    const float* b_hh2  = (const float*)d_in[9];
    const float* dzW1   = (const float*)d_in[10];
    const float* dzb1   = (const float*)d_in[11];
    const float* dzWloc = (const float*)d_in[12];
    const float* dzbloc = (const float*)d_in[13];
    const float* dzWsc  = (const float*)d_in[14];
    const float* dzbsc  = (const float*)d_in[15];
    const float* dxW1   = (const float*)d_in[16];
    const float* dxb1   = (const float*)d_in[17];
    const float* dxWloc = (const float*)d_in[18];
    const float* dxbloc = (const float*)d_in[19];
    const float* dxWsc  = (const float*)d_in[20];
    const float* dxbsc  = (const float*)d_in[21];
    const float* h1_0   = (const float*)d_in[22];
    const float* h2_0   = (const float*)d_in[23];

    scan_kernel<<<128, 64>>>(x, eps, W_ih1, W_hh1, b_ih1, b_hh1,
                             W_ih2, W_hh2, b_ih2, b_hh2,
                             dzW1, dzb1, dzWloc, dzbloc, dzWsc, dzbsc,
                             h1_0, h2_0, (float*)d_out);
    xhead_kernel<<<512, 256>>>(dxW1, dxb1, dxWloc, dxbloc, dxWsc, dxbsc,
                               (float*)d_out);
}